// round 8
// baseline (speedup 1.0000x reference)
#include <cuda_runtime.h>
#include <cuda_bf16.h>
#include <cstdint>

#define BB 8
#define NN 2048
#define DD 64
#define TIM 64               // i-rows per CTA (4 warps x 16)
#define KC 64                // j-chunk
#define NCHUNK (NN / KC)     // 32
#define PITCH 144            // smem H row pitch (bytes): conflict-free ldmatrix
#define MPITCH 272           // smem mask row pitch (bytes): 64 ints + 4 pad

// ---- dynamic smem layout (bytes) ----
#define MBUF (TIM * MPITCH)          // 17408 per buffer per mask
#define SM_MA 0                      // [2][MBUF]
#define SM_MJ (2 * MBUF)             // [2][MBUF]
#define SM_H  (4 * MBUF)             // [2][KC*PITCH = 9216]
#define SM_T  (SM_H + 2 * KC * PITCH)        // [2][256]
#define SM_V  (SM_T + 2 * 256)               // [2][256]
#define SMEM_TOTAL (SM_V + 2 * 256)          // 89088

// ---- device scratch ----
__device__ __nv_bfloat16 g_hb[BB * NN * DD];  // H: [n][d] bf16
__device__ float g_s[BB * NN];                // exp(a_src)
__device__ float g_t[BB * NN];                // exp(a_dst)
__device__ float g_u[BB * NN];                // exp(0.2*a_src)
__device__ float g_v[BB * NN];                // exp(0.2*a_dst)
__device__ float g_lam[2 * DD];               // lambda_adj[64], lambda_job[64]

// ---- PTX helpers (base-target instructions only) ----
__device__ __forceinline__ void mma_bf16(float* d,
    uint32_t a0, uint32_t a1, uint32_t a2, uint32_t a3, uint32_t b0, uint32_t b1) {
    asm volatile(
        "mma.sync.aligned.m16n8k16.row.col.f32.bf16.bf16.f32 "
        "{%0,%1,%2,%3}, {%4,%5,%6,%7}, {%8,%9}, {%0,%1,%2,%3};"
        : "+f"(d[0]), "+f"(d[1]), "+f"(d[2]), "+f"(d[3])
        : "r"(a0), "r"(a1), "r"(a2), "r"(a3), "r"(b0), "r"(b1));
}
__device__ __forceinline__ void ldsm4t(uint32_t& r0, uint32_t& r1, uint32_t& r2, uint32_t& r3, uint32_t addr) {
    asm volatile("ldmatrix.sync.aligned.m8n8.x4.trans.shared.b16 {%0,%1,%2,%3}, [%4];"
        : "=r"(r0), "=r"(r1), "=r"(r2), "=r"(r3) : "r"(addr));
}
__device__ __forceinline__ uint32_t packbf(float lo, float hi) {
    uint32_t r;
    asm("cvt.rn.satfinite.bf16x2.f32 %0, %1, %2;" : "=r"(r) : "f"(hi), "f"(lo));
    return r;
}
#define CP16(dst, src) asm volatile("cp.async.cg.shared.global [%0], [%1], 16;" :: "r"(dst), "l"(src))
#define CP_COMMIT()    asm volatile("cp.async.commit_group;" ::: "memory")
#define CP_WAIT1()     asm volatile("cp.async.wait_group 1;" ::: "memory")
#define CP_WAIT0()     asm volatile("cp.async.wait_group 0;" ::: "memory")

__device__ __forceinline__ float pvsel(float st, float uv) { return (st >= 1.0f) ? st : uv; }

// =====================================================================
// Kernel A: h = feats @ W^T (bf16), exps, lambdas.
// =====================================================================
__global__ __launch_bounds__(512) void prep_kernel(
    const float* __restrict__ feats, const float* __restrict__ W,
    const float* __restrict__ attn_src, const float* __restrict__ attn_dst,
    const float* __restrict__ lambda_params)
{
    __shared__ float sWt[DD * 66];   // sWt[d*66+o] = W[o][d]
    __shared__ float sF[16][DD];

    const int t = threadIdx.x;
    const int warp = t >> 5, lane = t & 31;
    const int o = lane * 2;
    const int row = blockIdx.x * 16 + warp;

    #pragma unroll
    for (int w = 0; w < 8; ++w) {
        int x = t + 512 * w;
        sWt[(x & 63) * 66 + (x >> 6)] = W[x];
    }
    *(float2*)&sF[warp][o] = *(const float2*)(feats + (size_t)row * DD + o);
    __syncthreads();

    float h0 = 0.f, h1 = 0.f;
    #pragma unroll
    for (int d = 0; d < DD; ++d) {
        const float fd = sF[warp][d];
        const float2 w2 = *(const float2*)&sWt[d * 66 + o];
        h0 = fmaf(fd, w2.x, h0);
        h1 = fmaf(fd, w2.y, h1);
    }

    *(__nv_bfloat162*)(g_hb + (size_t)row * DD + o) =
        __nv_bfloat162(__float2bfloat16(h0), __float2bfloat16(h1));

    const float2 ws = *(const float2*)(attn_src + o);
    const float2 wd = *(const float2*)(attn_dst + o);
    float rs = h0 * ws.x + h1 * ws.y;
    float rd = h0 * wd.x + h1 * wd.y;
    #pragma unroll
    for (int off = 16; off; off >>= 1) {
        rs += __shfl_down_sync(0xffffffffu, rs, off);
        rd += __shfl_down_sync(0xffffffffu, rd, off);
    }
    if (lane == 0) {
        g_s[row] = expf(rs);
        g_u[row] = expf(0.2f * rs);
        g_t[row] = expf(rd);
        g_v[row] = expf(0.2f * rd);
    }
    if (blockIdx.x == 0 && t >= 64 && t < 128) {
        int d = t - 64;
        float l0 = lambda_params[d * 2];
        float l1 = lambda_params[d * 2 + 1];
        float m = fmaxf(l0, l1);
        float e0 = expf(l0 - m), e1 = expf(l1 - m);
        float inv = 1.0f / (e0 + e1);
        g_lam[d] = e0 * inv;
        g_lam[DD + d] = e1 * inv;
    }
}

// =====================================================================
// Kernel B: HMMA dual-masked attention; masks streamed via cp.async
// grid = (NN/TIM=32, BB=8), 128 threads (4 warps x 16 rows)
// =====================================================================
__global__ __launch_bounds__(128, 2) void attn_hmma_kernel(
    const int* __restrict__ mask_adj, const int* __restrict__ mask_job,
    const int* __restrict__ bidx,
    const float* __restrict__ feats, float* __restrict__ out)
{
    extern __shared__ __align__(16) char smem[];
    __shared__ float sLamA[DD], sLamJ[DD];

    const int t = threadIdx.x;
    const int lane = t & 31, wid = t >> 5;
    const int b = blockIdx.y;
    const int i_base = blockIdx.x * TIM;
    const int bN = b * NN;

    int mb = bidx[b];                 // arange(B) identity gather; clamp defensively
    if (mb < 0 || mb >= BB) mb = b;

    if (t < DD) { sLamA[t] = g_lam[t]; sLamJ[t] = g_lam[DD + t]; }

    const int g  = lane >> 2;
    const int tq = lane & 3;
    const int r0 = wid * 16 + g;      // tile row 0..63
    const int r1 = r0 + 8;

    const float si0 = g_s[bN + i_base + r0], ui0 = g_u[bN + i_base + r0];
    const float si1 = g_s[bN + i_base + r1], ui1 = g_u[bN + i_base + r1];

    const uint32_t sub = (uint32_t)__cvta_generic_to_shared(smem);

    // staging identities: thread -> (row, half)
    const int srow = t >> 1, shalf = t & 1;
    const int* maSrc = mask_adj + ((size_t)mb * NN + i_base + srow) * NN + shalf * 32;
    const int* mjSrc = mask_job + ((size_t)mb * NN + i_base + srow) * NN + shalf * 32;
    const uint32_t maDst = sub + SM_MA + srow * MPITCH + shalf * 128;
    const uint32_t mjDst = sub + SM_MJ + srow * MPITCH + shalf * 128;
    const char* hSrc = (const char*)(g_hb + ((size_t)(bN + srow) << 6)) + shalf * 64;
    const uint32_t hDst = sub + SM_H + srow * PITCH + shalf * 64;

    auto stage = [&](int c, int s) {
        // masks: 64 rows x 256B each; this thread: 8x16B per mask
        const char* ma = (const char*)(maSrc + c * KC);
        const char* mj = (const char*)(mjSrc + c * KC);
        const uint32_t da = maDst + s * MBUF;
        const uint32_t dj = mjDst + s * MBUF;
        #pragma unroll
        for (int k = 0; k < 8; ++k) CP16(da + k * 16, ma + k * 16);
        #pragma unroll
        for (int k = 0; k < 8; ++k) CP16(dj + k * 16, mj + k * 16);
        // H: 64 rows x 128B
        const char* hp = hSrc + (size_t)c * KC * 128;
        const uint32_t dh = hDst + s * (KC * PITCH);
        CP16(dh,      hp);
        CP16(dh + 16, hp + 16);
        CP16(dh + 32, hp + 32);
        CP16(dh + 48, hp + 48);
        // t / v vectors
        if (t < 16) {
            CP16(sub + SM_T + s * 256 + t * 16, (const char*)(g_t + bN + c * KC) + t * 16);
        } else if (t < 32) {
            CP16(sub + SM_V + s * 256 + (t - 16) * 16, (const char*)(g_v + bN + c * KC) + (t - 16) * 16);
        }
    };

    // ldmatrix per-lane offset
    const int mid = lane >> 3, mrow = lane & 7;
    const int lmoff = ((mid & 1) * 8 + mrow) * PITCH + (mid >> 1) * 16;

    float accA[32], accJ[32];
    #pragma unroll
    for (int q = 0; q < 32; ++q) { accA[q] = 0.f; accJ[q] = 0.f; }
    float denA0 = 0.f, denA1 = 0.f, denJ0 = 0.f, denJ1 = 0.f;

    stage(0, 0);
    CP_COMMIT();

    for (int c = 0; c < NCHUNK; ++c) {
        const int s = c & 1;
        if (c + 1 < NCHUNK) {
            stage(c + 1, 1 - s);      // prev compute in that buffer finished at trailing sync
            CP_COMMIT();
            CP_WAIT1();               // current chunk arrived
        } else {
            CP_WAIT0();
        }
        __syncthreads();

        const char* mA = smem + SM_MA + s * MBUF;
        const char* mJ = smem + SM_MJ + s * MBUF;
        const uint32_t hbase = sub + SM_H + s * (KC * PITCH) + lmoff;
        const float* sTs = (const float*)(smem + SM_T + s * 256);
        const float* sVs = (const float*)(smem + SM_V + s * 256);

        #pragma unroll
        for (int kt = 0; kt < 4; ++kt) {
            const int jl = kt * 16;
            const int mo = kt * 64 + tq * 8;   // byte offset of j = 16kt + 2tq
            const int2 ma00 = *(const int2*)(mA + r0 * MPITCH + mo);
            const int2 ma0h = *(const int2*)(mA + r0 * MPITCH + mo + 32);
            const int2 ma10 = *(const int2*)(mA + r1 * MPITCH + mo);
            const int2 ma1h = *(const int2*)(mA + r1 * MPITCH + mo + 32);
            const int2 mj00 = *(const int2*)(mJ + r0 * MPITCH + mo);
            const int2 mj0h = *(const int2*)(mJ + r0 * MPITCH + mo + 32);
            const int2 mj10 = *(const int2*)(mJ + r1 * MPITCH + mo);
            const int2 mj1h = *(const int2*)(mJ + r1 * MPITCH + mo + 32);

            const float2 tlo = *(const float2*)&sTs[jl + 2 * tq];
            const float2 thi = *(const float2*)&sTs[jl + 2 * tq + 8];
            const float2 vlo = *(const float2*)&sVs[jl + 2 * tq];
            const float2 vhi = *(const float2*)&sVs[jl + 2 * tq + 8];

            const float pv00 = pvsel(si0 * tlo.x, ui0 * vlo.x);
            const float pv01 = pvsel(si0 * tlo.y, ui0 * vlo.y);
            const float pv0h0 = pvsel(si0 * thi.x, ui0 * vhi.x);
            const float pv0h1 = pvsel(si0 * thi.y, ui0 * vhi.y);
            const float pv10 = pvsel(si1 * tlo.x, ui1 * vlo.x);
            const float pv11 = pvsel(si1 * tlo.y, ui1 * vlo.y);
            const float pv1h0 = pvsel(si1 * thi.x, ui1 * vhi.x);
            const float pv1h1 = pvsel(si1 * thi.y, ui1 * vhi.y);

            const float A00 = ma00.x ? pv00 : 0.f,  A01 = ma00.y ? pv01 : 0.f;
            const float A0h0 = ma0h.x ? pv0h0 : 0.f, A0h1 = ma0h.y ? pv0h1 : 0.f;
            const float A10 = ma10.x ? pv10 : 0.f,  A11 = ma10.y ? pv11 : 0.f;
            const float A1h0 = ma1h.x ? pv1h0 : 0.f, A1h1 = ma1h.y ? pv1h1 : 0.f;
            const float J00 = mj00.x ? pv00 : 0.f,  J01 = mj00.y ? pv01 : 0.f;
            const float J0h0 = mj0h.x ? pv0h0 : 0.f, J0h1 = mj0h.y ? pv0h1 : 0.f;
            const float J10 = mj10.x ? pv10 : 0.f,  J11 = mj10.y ? pv11 : 0.f;
            const float J1h0 = mj1h.x ? pv1h0 : 0.f, J1h1 = mj1h.y ? pv1h1 : 0.f;

            denA0 += (A00 + A01) + (A0h0 + A0h1);
            denA1 += (A10 + A11) + (A1h0 + A1h1);
            denJ0 += (J00 + J01) + (J0h0 + J0h1);
            denJ1 += (J10 + J11) + (J1h0 + J1h1);

            const uint32_t aA0 = packbf(A00, A01),   aA1 = packbf(A10, A11);
            const uint32_t aA2 = packbf(A0h0, A0h1), aA3 = packbf(A1h0, A1h1);
            const uint32_t aJ0 = packbf(J00, J01),   aJ1 = packbf(J10, J11);
            const uint32_t aJ2 = packbf(J0h0, J0h1), aJ3 = packbf(J1h0, J1h1);

            const uint32_t hb = hbase + kt * (16 * PITCH);
            #pragma unroll
            for (int np = 0; np < 4; ++np) {
                uint32_t b0, b1, b2, b3;
                ldsm4t(b0, b1, b2, b3, hb + np * 32);
                mma_bf16(&accA[(2 * np) * 4],     aA0, aA1, aA2, aA3, b0, b1);
                mma_bf16(&accA[(2 * np + 1) * 4], aA0, aA1, aA2, aA3, b2, b3);
                mma_bf16(&accJ[(2 * np) * 4],     aJ0, aJ1, aJ2, aJ3, b0, b1);
                mma_bf16(&accJ[(2 * np + 1) * 4], aJ0, aJ1, aJ2, aJ3, b2, b3);
            }
        }
        __syncthreads();   // compute done before this buffer is re-staged
    }

    // denominator butterfly over the 4 lanes sharing g
    denA0 += __shfl_xor_sync(0xffffffffu, denA0, 1);
    denA0 += __shfl_xor_sync(0xffffffffu, denA0, 2);
    denA1 += __shfl_xor_sync(0xffffffffu, denA1, 1);
    denA1 += __shfl_xor_sync(0xffffffffu, denA1, 2);
    denJ0 += __shfl_xor_sync(0xffffffffu, denJ0, 1);
    denJ0 += __shfl_xor_sync(0xffffffffu, denJ0, 2);
    denJ1 += __shfl_xor_sync(0xffffffffu, denJ1, 1);
    denJ1 += __shfl_xor_sync(0xffffffffu, denJ1, 2);
    const float iA0 = 1.0f / denA0, iA1 = 1.0f / denA1;
    const float iJ0 = 1.0f / denJ0, iJ1 = 1.0f / denJ1;

    // epilogue: normalize + lambda blend + residual
    const float* f0 = feats + ((size_t)(bN + i_base + r0) << 6);
    const float* f1 = feats + ((size_t)(bN + i_base + r1) << 6);
    float* o0 = out + ((size_t)(bN + i_base + r0) << 6);
    float* o1 = out + ((size_t)(bN + i_base + r1) << 6);
    #pragma unroll
    for (int n = 0; n < 8; ++n) {
        const int c0 = n * 8 + 2 * tq;
        const float2 lA = *(const float2*)&sLamA[c0];
        const float2 lJ = *(const float2*)&sLamJ[c0];
        const float2 fr0 = *(const float2*)(f0 + c0);
        const float2 fr1 = *(const float2*)(f1 + c0);
        float2 q0, q1;
        q0.x = lA.x * accA[n * 4 + 0] * iA0 + lJ.x * accJ[n * 4 + 0] * iJ0 + fr0.x;
        q0.y = lA.y * accA[n * 4 + 1] * iA0 + lJ.y * accJ[n * 4 + 1] * iJ0 + fr0.y;
        q1.x = lA.x * accA[n * 4 + 2] * iA1 + lJ.x * accJ[n * 4 + 2] * iJ1 + fr1.x;
        q1.y = lA.y * accA[n * 4 + 3] * iA1 + lJ.y * accJ[n * 4 + 3] * iJ1 + fr1.y;
        *(float2*)(o0 + c0) = q0;
        *(float2*)(o1 + c0) = q1;
    }
}

extern "C" void kernel_launch(void* const* d_in, const int* in_sizes, int n_in,
                              void* d_out, int out_size) {
    (void)in_sizes; (void)n_in; (void)out_size;
    const int*   mask_adj      = (const int*)d_in[0];
    const int*   mask_job      = (const int*)d_in[1];
    const int*   bidx          = (const int*)d_in[2];
    const float* feats         = (const float*)d_in[3];
    const float* W             = (const float*)d_in[4];
    const float* attn_src      = (const float*)d_in[5];
    const float* attn_dst      = (const float*)d_in[6];
    const float* lambda_params = (const float*)d_in[7];
    float* out = (float*)d_out;

    static bool attr_set = false;
    if (!attr_set) {
        cudaFuncSetAttribute(attn_hmma_kernel,
                             cudaFuncAttributeMaxDynamicSharedMemorySize, SMEM_TOTAL);
        attr_set = true;
    }

    prep_kernel<<<BB * NN / 16, 512>>>(feats, W, attn_src, attn_dst, lambda_params);
    attn_hmma_kernel<<<dim3(NN / TIM, BB), 128, SMEM_TOTAL>>>(mask_adj, mask_job, bidx, feats, out);
}

// round 9
// speedup vs baseline: 1.1972x; 1.1972x over previous
#include <cuda_runtime.h>
#include <cuda_bf16.h>
#include <cstdint>

#define BB 8
#define NN 2048
#define DD 64
#define TIM 64               // i-rows per CTA (4 warps x 16)
#define KC 32                // j-chunk
#define NCHUNK (NN / KC)     // 64
#define SPLIT 4
#define CPS (NCHUNK / SPLIT) // 16 chunks per CTA
#define HPITCH 144           // smem H row pitch: conflict-free ldmatrix
#define MPITCH 144           // smem mask row pitch: 32 ints + 16B pad

// ---- dynamic smem layout (bytes) ----
#define MBUF (TIM * MPITCH)              // 9216 per buffer per mask
#define HBUF (KC * HPITCH)               // 4608 per buffer
#define SM_MA 0                          // [2][MBUF]
#define SM_MJ (2 * MBUF)                 // [2][MBUF]
#define SM_H  (4 * MBUF)                 // [2][HBUF]
#define SM_T  (SM_H + 2 * HBUF)          // [2][128]
#define SM_V  (SM_T + 2 * 128)           // [2][128]
#define SMEM_TOTAL (SM_V + 2 * 128)      // 46592 -> 4 CTAs/SM

// ---- device scratch ----
__device__ __nv_bfloat16 g_hb[BB * NN * DD];  // H: [n][d] bf16
__device__ float g_s[BB * NN];
__device__ float g_t[BB * NN];
__device__ float g_u[BB * NN];
__device__ float g_v[BB * NN];
__device__ float g_lam[2 * DD];
// split-K partials
__device__ float g_nA[SPLIT][BB * NN * DD];
__device__ float g_nJ[SPLIT][BB * NN * DD];
__device__ float g_dA[SPLIT][BB * NN];
__device__ float g_dJ[SPLIT][BB * NN];

// ---- PTX helpers (base-target instructions only) ----
__device__ __forceinline__ void mma_bf16(float* d,
    uint32_t a0, uint32_t a1, uint32_t a2, uint32_t a3, uint32_t b0, uint32_t b1) {
    asm volatile(
        "mma.sync.aligned.m16n8k16.row.col.f32.bf16.bf16.f32 "
        "{%0,%1,%2,%3}, {%4,%5,%6,%7}, {%8,%9}, {%0,%1,%2,%3};"
        : "+f"(d[0]), "+f"(d[1]), "+f"(d[2]), "+f"(d[3])
        : "r"(a0), "r"(a1), "r"(a2), "r"(a3), "r"(b0), "r"(b1));
}
__device__ __forceinline__ void ldsm4t(uint32_t& r0, uint32_t& r1, uint32_t& r2, uint32_t& r3, uint32_t addr) {
    asm volatile("ldmatrix.sync.aligned.m8n8.x4.trans.shared.b16 {%0,%1,%2,%3}, [%4];"
        : "=r"(r0), "=r"(r1), "=r"(r2), "=r"(r3) : "r"(addr));
}
__device__ __forceinline__ uint32_t packbf(float lo, float hi) {
    uint32_t r;
    asm("cvt.rn.satfinite.bf16x2.f32 %0, %1, %2;" : "=r"(r) : "f"(hi), "f"(lo));
    return r;
}
#define CP16(dst, src) asm volatile("cp.async.cg.shared.global [%0], [%1], 16;" :: "r"(dst), "l"(src))
#define CP_COMMIT()    asm volatile("cp.async.commit_group;" ::: "memory")
#define CP_WAIT1()     asm volatile("cp.async.wait_group 1;" ::: "memory")
#define CP_WAIT0()     asm volatile("cp.async.wait_group 0;" ::: "memory")

__device__ __forceinline__ float pvsel(float st, float uv) { return (st >= 1.0f) ? st : uv; }

// =====================================================================
// Kernel A: h = feats @ W^T (bf16), exps, lambdas.
// =====================================================================
__global__ __launch_bounds__(512) void prep_kernel(
    const float* __restrict__ feats, const float* __restrict__ W,
    const float* __restrict__ attn_src, const float* __restrict__ attn_dst,
    const float* __restrict__ lambda_params)
{
    __shared__ float sWt[DD * 66];
    __shared__ float sF[16][DD];

    const int t = threadIdx.x;
    const int warp = t >> 5, lane = t & 31;
    const int o = lane * 2;
    const int row = blockIdx.x * 16 + warp;

    #pragma unroll
    for (int w = 0; w < 8; ++w) {
        int x = t + 512 * w;
        sWt[(x & 63) * 66 + (x >> 6)] = W[x];
    }
    *(float2*)&sF[warp][o] = *(const float2*)(feats + (size_t)row * DD + o);
    __syncthreads();

    float h0 = 0.f, h1 = 0.f;
    #pragma unroll
    for (int d = 0; d < DD; ++d) {
        const float fd = sF[warp][d];
        const float2 w2 = *(const float2*)&sWt[d * 66 + o];
        h0 = fmaf(fd, w2.x, h0);
        h1 = fmaf(fd, w2.y, h1);
    }

    *(__nv_bfloat162*)(g_hb + (size_t)row * DD + o) =
        __nv_bfloat162(__float2bfloat16(h0), __float2bfloat16(h1));

    const float2 ws = *(const float2*)(attn_src + o);
    const float2 wd = *(const float2*)(attn_dst + o);
    float rs = h0 * ws.x + h1 * ws.y;
    float rd = h0 * wd.x + h1 * wd.y;
    #pragma unroll
    for (int off = 16; off; off >>= 1) {
        rs += __shfl_down_sync(0xffffffffu, rs, off);
        rd += __shfl_down_sync(0xffffffffu, rd, off);
    }
    if (lane == 0) {
        g_s[row] = expf(rs);
        g_u[row] = expf(0.2f * rs);
        g_t[row] = expf(rd);
        g_v[row] = expf(0.2f * rd);
    }
    if (blockIdx.x == 0 && t >= 64 && t < 128) {
        int d = t - 64;
        float l0 = lambda_params[d * 2];
        float l1 = lambda_params[d * 2 + 1];
        float m = fmaxf(l0, l1);
        float e0 = expf(l0 - m), e1 = expf(l1 - m);
        float inv = 1.0f / (e0 + e1);
        g_lam[d] = e0 * inv;
        g_lam[DD + d] = e1 * inv;
    }
}

// =====================================================================
// Kernel B: HMMA dual-masked attention, smem-staged masks, split-K
// grid = (NN/TIM=32, BB=8, SPLIT=4), 128 threads, 4 CTAs/SM
// =====================================================================
__global__ __launch_bounds__(128, 4) void attn_hmma_kernel(
    const int* __restrict__ mask_adj, const int* __restrict__ mask_job,
    const int* __restrict__ bidx)
{
    extern __shared__ __align__(16) char smem[];

    const int t = threadIdx.x;
    const int lane = t & 31, wid = t >> 5;
    const int b = blockIdx.y;
    const int sp = blockIdx.z;
    const int i_base = blockIdx.x * TIM;
    const int bN = b * NN;

    int mb = bidx[b];                 // arange(B) identity gather; clamp defensively
    if (mb < 0 || mb >= BB) mb = b;

    const int g  = lane >> 2;
    const int tq = lane & 3;
    const int r0 = wid * 16 + g;      // tile row 0..63
    const int r1 = r0 + 8;

    const float si0 = g_s[bN + i_base + r0], ui0 = g_u[bN + i_base + r0];
    const float si1 = g_s[bN + i_base + r1], ui1 = g_u[bN + i_base + r1];

    const uint32_t sub = (uint32_t)__cvta_generic_to_shared(smem);

    // staging identities
    const int srow = t >> 1, shalf = t & 1;          // masks: 64 rows x 2 halves (64B)
    const int* maSrc = mask_adj + ((size_t)mb * NN + i_base + srow) * NN + shalf * 16;
    const int* mjSrc = mask_job + ((size_t)mb * NN + i_base + srow) * NN + shalf * 16;
    const uint32_t maDst = sub + SM_MA + srow * MPITCH + shalf * 64;
    const uint32_t mjDst = sub + SM_MJ + srow * MPITCH + shalf * 64;
    const char* hSrc = (const char*)(g_hb + ((size_t)(bN + srow) << 6)) + shalf * 64; // rows 0..31 used
    const uint32_t hDst = sub + SM_H + srow * HPITCH + shalf * 64;

    auto stage = [&](int c, int s) {
        const char* ma = (const char*)(maSrc + c * KC);
        const char* mj = (const char*)(mjSrc + c * KC);
        const uint32_t da = maDst + s * MBUF;
        const uint32_t dj = mjDst + s * MBUF;
        #pragma unroll
        for (int k = 0; k < 4; ++k) CP16(da + k * 16, ma + k * 16);
        #pragma unroll
        for (int k = 0; k < 4; ++k) CP16(dj + k * 16, mj + k * 16);
        if (t < 64) {   // H: 32 rows x 128B
            const char* hp = hSrc + (size_t)c * KC * 128;
            const uint32_t dh = hDst + s * HBUF;
            CP16(dh,      hp);
            CP16(dh + 16, hp + 16);
            CP16(dh + 32, hp + 32);
            CP16(dh + 48, hp + 48);
        } else if (t < 72) {
            CP16(sub + SM_T + s * 128 + (t - 64) * 16, (const char*)(g_t + bN + c * KC) + (t - 64) * 16);
        } else if (t < 80) {
            CP16(sub + SM_V + s * 128 + (t - 72) * 16, (const char*)(g_v + bN + c * KC) + (t - 72) * 16);
        }
    };

    // ldmatrix per-lane offset
    const int mid = lane >> 3, mrow = lane & 7;
    const int lmoff = ((mid & 1) * 8 + mrow) * HPITCH + (mid >> 1) * 16;

    float accA[32], accJ[32];
    #pragma unroll
    for (int q = 0; q < 32; ++q) { accA[q] = 0.f; accJ[q] = 0.f; }
    float denA0 = 0.f, denA1 = 0.f, denJ0 = 0.f, denJ1 = 0.f;

    const int c0 = sp * CPS;
    stage(c0, 0);
    CP_COMMIT();

    for (int ci = 0; ci < CPS; ++ci) {
        const int c = c0 + ci;
        const int s = ci & 1;
        if (ci + 1 < CPS) {
            stage(c + 1, 1 - s);
            CP_COMMIT();
            CP_WAIT1();
        } else {
            CP_WAIT0();
        }
        __syncthreads();

        const char* mA = smem + SM_MA + s * MBUF;
        const char* mJ = smem + SM_MJ + s * MBUF;
        const uint32_t hbase = sub + SM_H + s * HBUF + lmoff;
        const float* sTs = (const float*)(smem + SM_T + s * 128);
        const float* sVs = (const float*)(smem + SM_V + s * 128);

        #pragma unroll
        for (int kt = 0; kt < 2; ++kt) {
            const int jl = kt * 16;
            const int mo = kt * 64 + tq * 8;
            const int2 ma00 = *(const int2*)(mA + r0 * MPITCH + mo);
            const int2 ma0h = *(const int2*)(mA + r0 * MPITCH + mo + 32);
            const int2 ma10 = *(const int2*)(mA + r1 * MPITCH + mo);
            const int2 ma1h = *(const int2*)(mA + r1 * MPITCH + mo + 32);
            const int2 mj00 = *(const int2*)(mJ + r0 * MPITCH + mo);
            const int2 mj0h = *(const int2*)(mJ + r0 * MPITCH + mo + 32);
            const int2 mj10 = *(const int2*)(mJ + r1 * MPITCH + mo);
            const int2 mj1h = *(const int2*)(mJ + r1 * MPITCH + mo + 32);

            const float2 tlo = *(const float2*)&sTs[jl + 2 * tq];
            const float2 thi = *(const float2*)&sTs[jl + 2 * tq + 8];
            const float2 vlo = *(const float2*)&sVs[jl + 2 * tq];
            const float2 vhi = *(const float2*)&sVs[jl + 2 * tq + 8];

            const float pv00 = pvsel(si0 * tlo.x, ui0 * vlo.x);
            const float pv01 = pvsel(si0 * tlo.y, ui0 * vlo.y);
            const float pv0h0 = pvsel(si0 * thi.x, ui0 * vhi.x);
            const float pv0h1 = pvsel(si0 * thi.y, ui0 * vhi.y);
            const float pv10 = pvsel(si1 * tlo.x, ui1 * vlo.x);
            const float pv11 = pvsel(si1 * tlo.y, ui1 * vlo.y);
            const float pv1h0 = pvsel(si1 * thi.x, ui1 * vhi.x);
            const float pv1h1 = pvsel(si1 * thi.y, ui1 * vhi.y);

            const float A00 = ma00.x ? pv00 : 0.f,  A01 = ma00.y ? pv01 : 0.f;
            const float A0h0 = ma0h.x ? pv0h0 : 0.f, A0h1 = ma0h.y ? pv0h1 : 0.f;
            const float A10 = ma10.x ? pv10 : 0.f,  A11 = ma10.y ? pv11 : 0.f;
            const float A1h0 = ma1h.x ? pv1h0 : 0.f, A1h1 = ma1h.y ? pv1h1 : 0.f;
            const float J00 = mj00.x ? pv00 : 0.f,  J01 = mj00.y ? pv01 : 0.f;
            const float J0h0 = mj0h.x ? pv0h0 : 0.f, J0h1 = mj0h.y ? pv0h1 : 0.f;
            const float J10 = mj10.x ? pv10 : 0.f,  J11 = mj10.y ? pv11 : 0.f;
            const float J1h0 = mj1h.x ? pv1h0 : 0.f, J1h1 = mj1h.y ? pv1h1 : 0.f;

            denA0 += (A00 + A01) + (A0h0 + A0h1);
            denA1 += (A10 + A11) + (A1h0 + A1h1);
            denJ0 += (J00 + J01) + (J0h0 + J0h1);
            denJ1 += (J10 + J11) + (J1h0 + J1h1);

            const uint32_t aA0 = packbf(A00, A01),   aA1 = packbf(A10, A11);
            const uint32_t aA2 = packbf(A0h0, A0h1), aA3 = packbf(A1h0, A1h1);
            const uint32_t aJ0 = packbf(J00, J01),   aJ1 = packbf(J10, J11);
            const uint32_t aJ2 = packbf(J0h0, J0h1), aJ3 = packbf(J1h0, J1h1);

            const uint32_t hb = hbase + kt * (16 * HPITCH);
            #pragma unroll
            for (int np = 0; np < 4; ++np) {
                uint32_t b0, b1, b2, b3;
                ldsm4t(b0, b1, b2, b3, hb + np * 32);
                mma_bf16(&accA[(2 * np) * 4],     aA0, aA1, aA2, aA3, b0, b1);
                mma_bf16(&accA[(2 * np + 1) * 4], aA0, aA1, aA2, aA3, b2, b3);
                mma_bf16(&accJ[(2 * np) * 4],     aJ0, aJ1, aJ2, aJ3, b0, b1);
                mma_bf16(&accJ[(2 * np + 1) * 4], aJ0, aJ1, aJ2, aJ3, b2, b3);
            }
        }
        __syncthreads();
    }

    // denominator butterfly over the 4 lanes sharing g
    denA0 += __shfl_xor_sync(0xffffffffu, denA0, 1);
    denA0 += __shfl_xor_sync(0xffffffffu, denA0, 2);
    denA1 += __shfl_xor_sync(0xffffffffu, denA1, 1);
    denA1 += __shfl_xor_sync(0xffffffffu, denA1, 2);
    denJ0 += __shfl_xor_sync(0xffffffffu, denJ0, 1);
    denJ0 += __shfl_xor_sync(0xffffffffu, denJ0, 2);
    denJ1 += __shfl_xor_sync(0xffffffffu, denJ1, 1);
    denJ1 += __shfl_xor_sync(0xffffffffu, denJ1, 2);

    // write partials
    float* nA = g_nA[sp];
    float* nJ = g_nJ[sp];
    const size_t o0b = (size_t)(bN + i_base + r0) << 6;
    const size_t o1b = (size_t)(bN + i_base + r1) << 6;
    #pragma unroll
    for (int n = 0; n < 8; ++n) {
        const int cc = n * 8 + 2 * tq;
        *(float2*)(nA + o0b + cc) = make_float2(accA[n * 4 + 0], accA[n * 4 + 1]);
        *(float2*)(nA + o1b + cc) = make_float2(accA[n * 4 + 2], accA[n * 4 + 3]);
        *(float2*)(nJ + o0b + cc) = make_float2(accJ[n * 4 + 0], accJ[n * 4 + 1]);
        *(float2*)(nJ + o1b + cc) = make_float2(accJ[n * 4 + 2], accJ[n * 4 + 3]);
    }
    if (tq == 0) {
        g_dA[sp][bN + i_base + r0] = denA0;
        g_dA[sp][bN + i_base + r1] = denA1;
        g_dJ[sp][bN + i_base + r0] = denJ0;
        g_dJ[sp][bN + i_base + r1] = denJ1;
    }
}

// =====================================================================
// Kernel C: combine splits, normalize, blend, residual
// =====================================================================
__global__ __launch_bounds__(256) void combine_kernel(
    const float* __restrict__ feats, float* __restrict__ out)
{
    const int idx = (blockIdx.x * blockDim.x + threadIdx.x) * 4;
    const int n = idx >> 6;
    const int d = idx & 63;

    float4 na = make_float4(0.f, 0.f, 0.f, 0.f);
    float4 nj = make_float4(0.f, 0.f, 0.f, 0.f);
    float da = 0.f, dj = 0.f;
    #pragma unroll
    for (int sp = 0; sp < SPLIT; ++sp) {
        const float4 a = *(const float4*)(g_nA[sp] + idx);
        const float4 j = *(const float4*)(g_nJ[sp] + idx);
        na.x += a.x; na.y += a.y; na.z += a.z; na.w += a.w;
        nj.x += j.x; nj.y += j.y; nj.z += j.z; nj.w += j.w;
        da += g_dA[sp][n];
        dj += g_dJ[sp][n];
    }
    const float ra = 1.0f / da;
    const float rj = 1.0f / dj;
    const float4 lA = *(const float4*)&g_lam[d];
    const float4 lJ = *(const float4*)&g_lam[DD + d];
    const float4 f = *(const float4*)(feats + idx);
    float4 o;
    o.x = lA.x * na.x * ra + lJ.x * nj.x * rj + f.x;
    o.y = lA.y * na.y * ra + lJ.y * nj.y * rj + f.y;
    o.z = lA.z * na.z * ra + lJ.z * nj.z * rj + f.z;
    o.w = lA.w * na.w * ra + lJ.w * nj.w * rj + f.w;
    *(float4*)(out + idx) = o;
}

extern "C" void kernel_launch(void* const* d_in, const int* in_sizes, int n_in,
                              void* d_out, int out_size) {
    (void)in_sizes; (void)n_in; (void)out_size;
    const int*   mask_adj      = (const int*)d_in[0];
    const int*   mask_job      = (const int*)d_in[1];
    const int*   bidx          = (const int*)d_in[2];
    const float* feats         = (const float*)d_in[3];
    const float* W             = (const float*)d_in[4];
    const float* attn_src      = (const float*)d_in[5];
    const float* attn_dst      = (const float*)d_in[6];
    const float* lambda_params = (const float*)d_in[7];
    float* out = (float*)d_out;

    prep_kernel<<<BB * NN / 16, 512>>>(feats, W, attn_src, attn_dst, lambda_params);
    attn_hmma_kernel<<<dim3(NN / TIM, BB, SPLIT), 128, SMEM_TOTAL>>>(mask_adj, mask_job, bidx);
    combine_kernel<<<BB * NN * DD / 4 / 256, 256>>>(feats, out);
}

// round 10
// speedup vs baseline: 1.2448x; 1.0397x over previous
#include <cuda_runtime.h>
#include <cuda_bf16.h>
#include <cstdint>

#define BB 8
#define NN 2048
#define DD 64
#define TIM 64               // i-rows per CTA (4 warps x 16)
#define KC 32                // j-chunk
#define NCHUNK (NN / KC)     // 64
#define SPLIT 4
#define CPS (NCHUNK / SPLIT) // 16 chunks per CTA
#define HPITCH 144           // smem H row pitch: conflict-free ldmatrix
#define MPITCH 144           // smem mask row pitch

// ---- dynamic smem layout (bytes) ----
#define MBUF (TIM * MPITCH)              // 9216 per buffer per mask
#define HBUF (KC * HPITCH)               // 4608 per buffer
#define SM_MA 0                          // [2][MBUF]
#define SM_MJ (2 * MBUF)                 // [2][MBUF]
#define SM_H  (4 * MBUF)                 // [2][HBUF]
#define SM_T  (SM_H + 2 * HBUF)          // [2][128]
#define SM_V  (SM_T + 2 * 128)           // [2][128]
#define SMEM_TOTAL (SM_V + 2 * 128)      // 46592 -> 4 CTAs/SM

// ---- device scratch ----
__device__ __nv_bfloat16 g_hb[BB * NN * DD];  // H: [n][d] bf16
__device__ float g_s[BB * NN];
__device__ float g_t[BB * NN];
__device__ float g_u[BB * NN];
__device__ float g_v[BB * NN];
__device__ float g_lam[2 * DD];
// split-K partials
__device__ float g_nA[SPLIT][BB * NN * DD];
__device__ float g_nJ[SPLIT][BB * NN * DD];
__device__ float g_dA[SPLIT][BB * NN];
__device__ float g_dJ[SPLIT][BB * NN];

// ---- PTX helpers (base-target instructions only) ----
__device__ __forceinline__ void mma_bf16(float* d,
    uint32_t a0, uint32_t a1, uint32_t a2, uint32_t a3, uint32_t b0, uint32_t b1) {
    asm volatile(
        "mma.sync.aligned.m16n8k16.row.col.f32.bf16.bf16.f32 "
        "{%0,%1,%2,%3}, {%4,%5,%6,%7}, {%8,%9}, {%0,%1,%2,%3};"
        : "+f"(d[0]), "+f"(d[1]), "+f"(d[2]), "+f"(d[3])
        : "r"(a0), "r"(a1), "r"(a2), "r"(a3), "r"(b0), "r"(b1));
}
__device__ __forceinline__ void ldsm4t(uint32_t& r0, uint32_t& r1, uint32_t& r2, uint32_t& r3, uint32_t addr) {
    asm volatile("ldmatrix.sync.aligned.m8n8.x4.trans.shared.b16 {%0,%1,%2,%3}, [%4];"
        : "=r"(r0), "=r"(r1), "=r"(r2), "=r"(r3) : "r"(addr));
}
__device__ __forceinline__ uint32_t packbf(float lo, float hi) {
    uint32_t r;
    asm("cvt.rn.satfinite.bf16x2.f32 %0, %1, %2;" : "=r"(r) : "f"(hi), "f"(lo));
    return r;
}
#define CP16(dst, src) asm volatile("cp.async.cg.shared.global [%0], [%1], 16;" :: "r"(dst), "l"(src))
#define CP_COMMIT()    asm volatile("cp.async.commit_group;" ::: "memory")
#define CP_WAIT1()     asm volatile("cp.async.wait_group 1;" ::: "memory")
#define CP_WAIT0()     asm volatile("cp.async.wait_group 0;" ::: "memory")

__device__ __forceinline__ float pvsel(float st, float uv) { return (st >= 1.0f) ? st : uv; }

// j-permutation: HMMA k-slot kk (0..15) -> global j within 16-block.
// Lane tq owns k = {2tq, 2tq+1, 2tq+8, 2tq+9} -> j = {4tq..4tq+3} (contiguous).
__device__ __forceinline__ int psi(int kk) {
    return (((kk >> 1) & 3) << 2) + ((kk >> 3) << 1) + (kk & 1);
}

// =====================================================================
// Kernel A: h = feats @ W^T (bf16), exps, lambdas.
// 512 threads = 16 warps; warp = 4 rows; lane = 2 cols x 4 rows.
// grid = B*N/64
// =====================================================================
__global__ __launch_bounds__(512) void prep_kernel(
    const float* __restrict__ feats, const float* __restrict__ W,
    const float* __restrict__ attn_src, const float* __restrict__ attn_dst,
    const float* __restrict__ lambda_params)
{
    __shared__ float sWt[DD * 66];   // sWt[d*66+o] = W[o][d]
    __shared__ float sF[64 * DD];    // 64 rows, row-major

    const int t = threadIdx.x;
    const int warp = t >> 5, lane = t & 31;
    const int o = lane * 2;
    const int row0 = blockIdx.x * 64;
    const int rb = warp * 4;         // warp's first local row

    #pragma unroll
    for (int w = 0; w < 8; ++w) {
        int x = t + 512 * w;
        sWt[(x & 63) * 66 + (x >> 6)] = W[x];
    }
    #pragma unroll
    for (int w = 0; w < 2; ++w) {
        const int x4 = t + 512 * w;                       // 1024 float4s
        *(float4*)&sF[x4 * 4] = *(const float4*)(feats + (size_t)row0 * DD + x4 * 4);
    }
    __syncthreads();

    float h[4][2];
    #pragma unroll
    for (int r = 0; r < 4; ++r) { h[r][0] = 0.f; h[r][1] = 0.f; }

    #pragma unroll
    for (int d = 0; d < DD; ++d) {
        const float2 w2 = *(const float2*)&sWt[d * 66 + o];
        #pragma unroll
        for (int r = 0; r < 4; ++r) {
            const float fd = sF[(rb + r) * DD + d];
            h[r][0] = fmaf(fd, w2.x, h[r][0]);
            h[r][1] = fmaf(fd, w2.y, h[r][1]);
        }
    }

    #pragma unroll
    for (int r = 0; r < 4; ++r) {
        *(__nv_bfloat162*)(g_hb + (size_t)(row0 + rb + r) * DD + o) =
            __nv_bfloat162(__float2bfloat16(h[r][0]), __float2bfloat16(h[r][1]));
    }

    const float2 ws = *(const float2*)(attn_src + o);
    const float2 wd = *(const float2*)(attn_dst + o);
    float rs[4], rd[4];
    #pragma unroll
    for (int r = 0; r < 4; ++r) {
        rs[r] = h[r][0] * ws.x + h[r][1] * ws.y;
        rd[r] = h[r][0] * wd.x + h[r][1] * wd.y;
    }
    #pragma unroll
    for (int off = 16; off; off >>= 1) {
        #pragma unroll
        for (int r = 0; r < 4; ++r) {
            rs[r] += __shfl_down_sync(0xffffffffu, rs[r], off);
            rd[r] += __shfl_down_sync(0xffffffffu, rd[r], off);
        }
    }
    if (lane == 0) {
        #pragma unroll
        for (int r = 0; r < 4; ++r) {
            const int n = row0 + rb + r;
            g_s[n] = expf(rs[r]);
            g_u[n] = expf(0.2f * rs[r]);
            g_t[n] = expf(rd[r]);
            g_v[n] = expf(0.2f * rd[r]);
        }
    }
    if (blockIdx.x == 0 && t >= 64 && t < 128) {
        int d = t - 64;
        float l0 = lambda_params[d * 2];
        float l1 = lambda_params[d * 2 + 1];
        float m = fmaxf(l0, l1);
        float e0 = expf(l0 - m), e1 = expf(l1 - m);
        float inv = 1.0f / (e0 + e1);
        g_lam[d] = e0 * inv;
        g_lam[DD + d] = e1 * inv;
    }
}

// =====================================================================
// Kernel B: HMMA dual-masked attention, smem masks, split-K, j-permuted
// grid = (NN/TIM=32, BB=8, SPLIT=4), 128 threads, 4 CTAs/SM
// =====================================================================
__global__ __launch_bounds__(128, 4) void attn_hmma_kernel(
    const int* __restrict__ mask_adj, const int* __restrict__ mask_job,
    const int* __restrict__ bidx)
{
    extern __shared__ __align__(16) char smem[];

    const int t = threadIdx.x;
    const int lane = t & 31, wid = t >> 5;
    const int b = blockIdx.y;
    const int sp = blockIdx.z;
    const int i_base = blockIdx.x * TIM;
    const int bN = b * NN;

    int mb = bidx[b];                 // arange(B) identity gather; clamp defensively
    if (mb < 0 || mb >= BB) mb = b;

    const int g  = lane >> 2;
    const int tq = lane & 3;
    const int r0 = wid * 16 + g;      // tile row 0..63
    const int r1 = r0 + 8;

    const float si0 = g_s[bN + i_base + r0], ui0 = g_u[bN + i_base + r0];
    const float si1 = g_s[bN + i_base + r1], ui1 = g_u[bN + i_base + r1];

    const uint32_t sub = (uint32_t)__cvta_generic_to_shared(smem);

    // staging identities
    const int srow = t >> 1, shalf = t & 1;          // masks: 64 rows x 2 halves (64B)
    const int* maSrc = mask_adj + ((size_t)mb * NN + i_base + srow) * NN + shalf * 16;
    const int* mjSrc = mask_job + ((size_t)mb * NN + i_base + srow) * NN + shalf * 16;
    const uint32_t maDst = sub + SM_MA + srow * MPITCH + shalf * 64;
    const uint32_t mjDst = sub + SM_MJ + srow * MPITCH + shalf * 64;
    // H: smem row r holds global j-row (r&16) + psi(r&15) within the chunk
    const int srowp = (srow & 16) | psi(srow & 15);
    const char* hSrc = (const char*)(g_hb + ((size_t)(bN + srowp) << 6)) + shalf * 64;
    const uint32_t hDst = sub + SM_H + srow * HPITCH + shalf * 64;

    auto stage = [&](int c, int s) {
        const char* ma = (const char*)(maSrc + c * KC);
        const char* mj = (const char*)(mjSrc + c * KC);
        const uint32_t da = maDst + s * MBUF;
        const uint32_t dj = mjDst + s * MBUF;
        #pragma unroll
        for (int k = 0; k < 4; ++k) CP16(da + k * 16, ma + k * 16);
        #pragma unroll
        for (int k = 0; k < 4; ++k) CP16(dj + k * 16, mj + k * 16);
        if (t < 64) {   // H: 32 rows x 128B (row-permuted source)
            const char* hp = hSrc + (size_t)c * KC * 128;
            const uint32_t dh = hDst + s * HBUF;
            CP16(dh,      hp);
            CP16(dh + 16, hp + 16);
            CP16(dh + 32, hp + 32);
            CP16(dh + 48, hp + 48);
        } else if (t < 72) {
            CP16(sub + SM_T + s * 128 + (t - 64) * 16, (const char*)(g_t + bN + c * KC) + (t - 64) * 16);
        } else if (t < 80) {
            CP16(sub + SM_V + s * 128 + (t - 72) * 16, (const char*)(g_v + bN + c * KC) + (t - 72) * 16);
        }
    };

    // ldmatrix per-lane offset (smem row = k index, unchanged)
    const int mid = lane >> 3, mrow = lane & 7;
    const int lmoff = ((mid & 1) * 8 + mrow) * HPITCH + (mid >> 1) * 16;

    float accA[32], accJ[32];
    #pragma unroll
    for (int q = 0; q < 32; ++q) { accA[q] = 0.f; accJ[q] = 0.f; }
    float denA0 = 0.f, denA1 = 0.f, denJ0 = 0.f, denJ1 = 0.f;

    const int c0 = sp * CPS;
    stage(c0, 0);
    CP_COMMIT();

    for (int ci = 0; ci < CPS; ++ci) {
        const int c = c0 + ci;
        const int s = ci & 1;
        if (ci + 1 < CPS) {
            stage(c + 1, 1 - s);
            CP_COMMIT();
            CP_WAIT1();
        } else {
            CP_WAIT0();
        }
        __syncthreads();

        const char* mA = smem + SM_MA + s * MBUF;
        const char* mJ = smem + SM_MJ + s * MBUF;
        const uint32_t hbase = sub + SM_H + s * HBUF + lmoff;
        const float* sTs = (const float*)(smem + SM_T + s * 128);
        const float* sVs = (const float*)(smem + SM_V + s * 128);

        #pragma unroll
        for (int kt = 0; kt < 2; ++kt) {
            const int mo = kt * 64 + tq * 16;         // one int4: j = 16kt + 4tq + 0..3
            const int4 ma0 = *(const int4*)(mA + r0 * MPITCH + mo);
            const int4 ma1 = *(const int4*)(mA + r1 * MPITCH + mo);
            const int4 mj0 = *(const int4*)(mJ + r0 * MPITCH + mo);
            const int4 mj1 = *(const int4*)(mJ + r1 * MPITCH + mo);

            const float4 t4 = *(const float4*)&sTs[kt * 16 + 4 * tq];
            const float4 v4 = *(const float4*)&sVs[kt * 16 + 4 * tq];

            // pv per (row, j): exp(leaky(e)) = st if st>=1 else uv
            const float pv00 = pvsel(si0 * t4.x, ui0 * v4.x);
            const float pv01 = pvsel(si0 * t4.y, ui0 * v4.y);
            const float pv02 = pvsel(si0 * t4.z, ui0 * v4.z);
            const float pv03 = pvsel(si0 * t4.w, ui0 * v4.w);
            const float pv10 = pvsel(si1 * t4.x, ui1 * v4.x);
            const float pv11 = pvsel(si1 * t4.y, ui1 * v4.y);
            const float pv12 = pvsel(si1 * t4.z, ui1 * v4.z);
            const float pv13 = pvsel(si1 * t4.w, ui1 * v4.w);

            const float A00 = ma0.x ? pv00 : 0.f, A01 = ma0.y ? pv01 : 0.f;
            const float A02 = ma0.z ? pv02 : 0.f, A03 = ma0.w ? pv03 : 0.f;
            const float A10 = ma1.x ? pv10 : 0.f, A11 = ma1.y ? pv11 : 0.f;
            const float A12 = ma1.z ? pv12 : 0.f, A13 = ma1.w ? pv13 : 0.f;
            const float J00 = mj0.x ? pv00 : 0.f, J01 = mj0.y ? pv01 : 0.f;
            const float J02 = mj0.z ? pv02 : 0.f, J03 = mj0.w ? pv03 : 0.f;
            const float J10 = mj1.x ? pv10 : 0.f, J11 = mj1.y ? pv11 : 0.f;
            const float J12 = mj1.z ? pv12 : 0.f, J13 = mj1.w ? pv13 : 0.f;

            denA0 += (A00 + A01) + (A02 + A03);
            denA1 += (A10 + A11) + (A12 + A13);
            denJ0 += (J00 + J01) + (J02 + J03);
            denJ1 += (J10 + J11) + (J12 + J13);

            // A-frag: a0 = (k=2tq, 2tq+1) -> j 4tq,4tq+1; a2 = (k+8) -> j 4tq+2,4tq+3
            const uint32_t aA0 = packbf(A00, A01), aA1 = packbf(A10, A11);
            const uint32_t aA2 = packbf(A02, A03), aA3 = packbf(A12, A13);
            const uint32_t aJ0 = packbf(J00, J01), aJ1 = packbf(J10, J11);
            const uint32_t aJ2 = packbf(J02, J03), aJ3 = packbf(J12, J13);

            const uint32_t hb = hbase + kt * (16 * HPITCH);
            #pragma unroll
            for (int np = 0; np < 4; ++np) {
                uint32_t b0, b1, b2, b3;
                ldsm4t(b0, b1, b2, b3, hb + np * 32);
                mma_bf16(&accA[(2 * np) * 4],     aA0, aA1, aA2, aA3, b0, b1);
                mma_bf16(&accA[(2 * np + 1) * 4], aA0, aA1, aA2, aA3, b2, b3);
                mma_bf16(&accJ[(2 * np) * 4],     aJ0, aJ1, aJ2, aJ3, b0, b1);
                mma_bf16(&accJ[(2 * np + 1) * 4], aJ0, aJ1, aJ2, aJ3, b2, b3);
            }
        }
        __syncthreads();
    }

    // denominator butterfly over the 4 lanes sharing g
    denA0 += __shfl_xor_sync(0xffffffffu, denA0, 1);
    denA0 += __shfl_xor_sync(0xffffffffu, denA0, 2);
    denA1 += __shfl_xor_sync(0xffffffffu, denA1, 1);
    denA1 += __shfl_xor_sync(0xffffffffu, denA1, 2);
    denJ0 += __shfl_xor_sync(0xffffffffu, denJ0, 1);
    denJ0 += __shfl_xor_sync(0xffffffffu, denJ0, 2);
    denJ1 += __shfl_xor_sync(0xffffffffu, denJ1, 1);
    denJ1 += __shfl_xor_sync(0xffffffffu, denJ1, 2);

    // write partials
    float* nA = g_nA[sp];
    float* nJ = g_nJ[sp];
    const size_t o0b = (size_t)(bN + i_base + r0) << 6;
    const size_t o1b = (size_t)(bN + i_base + r1) << 6;
    #pragma unroll
    for (int n = 0; n < 8; ++n) {
        const int cc = n * 8 + 2 * tq;
        *(float2*)(nA + o0b + cc) = make_float2(accA[n * 4 + 0], accA[n * 4 + 1]);
        *(float2*)(nA + o1b + cc) = make_float2(accA[n * 4 + 2], accA[n * 4 + 3]);
        *(float2*)(nJ + o0b + cc) = make_float2(accJ[n * 4 + 0], accJ[n * 4 + 1]);
        *(float2*)(nJ + o1b + cc) = make_float2(accJ[n * 4 + 2], accJ[n * 4 + 3]);
    }
    if (tq == 0) {
        g_dA[sp][bN + i_base + r0] = denA0;
        g_dA[sp][bN + i_base + r1] = denA1;
        g_dJ[sp][bN + i_base + r0] = denJ0;
        g_dJ[sp][bN + i_base + r1] = denJ1;
    }
}

// =====================================================================
// Kernel C: combine splits, normalize, blend, residual
// =====================================================================
__global__ __launch_bounds__(256) void combine_kernel(
    const float* __restrict__ feats, float* __restrict__ out)
{
    const int idx = (blockIdx.x * blockDim.x + threadIdx.x) * 4;
    const int n = idx >> 6;
    const int d = idx & 63;

    float4 na = make_float4(0.f, 0.f, 0.f, 0.f);
    float4 nj = make_float4(0.f, 0.f, 0.f, 0.f);
    float da = 0.f, dj = 0.f;
    #pragma unroll
    for (int sp = 0; sp < SPLIT; ++sp) {
        const float4 a = *(const float4*)(g_nA[sp] + idx);
        const float4 j = *(const float4*)(g_nJ[sp] + idx);
        na.x += a.x; na.y += a.y; na.z += a.z; na.w += a.w;
        nj.x += j.x; nj.y += j.y; nj.z += j.z; nj.w += j.w;
        da += g_dA[sp][n];
        dj += g_dJ[sp][n];
    }
    const float ra = 1.0f / da;
    const float rj = 1.0f / dj;
    const float4 lA = *(const float4*)&g_lam[d];
    const float4 lJ = *(const float4*)&g_lam[DD + d];
    const float4 f = *(const float4*)(feats + idx);
    float4 o;
    o.x = lA.x * na.x * ra + lJ.x * nj.x * rj + f.x;
    o.y = lA.y * na.y * ra + lJ.y * nj.y * rj + f.y;
    o.z = lA.z * na.z * ra + lJ.z * nj.z * rj + f.z;
    o.w = lA.w * na.w * ra + lJ.w * nj.w * rj + f.w;
    *(float4*)(out + idx) = o;
}

extern "C" void kernel_launch(void* const* d_in, const int* in_sizes, int n_in,
                              void* d_out, int out_size) {
    (void)in_sizes; (void)n_in; (void)out_size;
    const int*   mask_adj      = (const int*)d_in[0];
    const int*   mask_job      = (const int*)d_in[1];
    const int*   bidx          = (const int*)d_in[2];
    const float* feats         = (const float*)d_in[3];
    const float* W             = (const float*)d_in[4];
    const float* attn_src      = (const float*)d_in[5];
    const float* attn_dst      = (const float*)d_in[6];
    const float* lambda_params = (const float*)d_in[7];
    float* out = (float*)d_out;

    prep_kernel<<<BB * NN / 64, 512>>>(feats, W, attn_src, attn_dst, lambda_params);
    attn_hmma_kernel<<<dim3(NN / TIM, BB, SPLIT), 128, SMEM_TOTAL>>>(mask_adj, mask_job, bidx);
    combine_kernel<<<BB * NN * DD / 4 / 256, 256>>>(feats, out);
}